// round 5
// baseline (speedup 1.0000x reference)
#include <cuda_runtime.h>
#include <cstdint>

// Problem constants (fixed by the dataset): N=100000 nodes, D=C=128.
#define NN 100000

// Scratch (device globals — no allocations allowed anywhere).
__device__ __align__(16) float g_dinv[NN];              // rsqrt(degree)
__device__ __align__(16) float g_xw[(size_t)NN * 256];  // reused: l1a, xw1, xw2
__device__ __align__(16) float g_g1[(size_t)NN * 256];  // gcn1 output
__device__ __align__(16) float g_g2[(size_t)NN * 128];  // gcn2 output

// Buffer ids for device-side resolution (avoid cudaGetSymbolAddress entirely).
#define BUF_NONE 0
#define BUF_XW   1
#define BUF_G1   2
#define BUF_G2   3

__device__ __forceinline__ float* resolve(float* p, int id) {
    switch (id) {
        case BUF_XW: return g_xw;
        case BUF_G1: return g_g1;
        case BUF_G2: return g_g2;
        default: return p;
    }
}
__device__ __forceinline__ const float* resolve_c(const float* p, int id) {
    switch (id) {
        case BUF_XW: return g_xw;
        case BUF_G1: return g_g1;
        case BUF_G2: return g_g2;
        default: return p;
    }
}

// ---------------------------------------------------------------------------
// Degree / normalization (operate directly on g_dinv)
// ---------------------------------------------------------------------------
__global__ void deg_init_kernel(int n) {
    int i = blockIdx.x * blockDim.x + threadIdx.x;
    if (i < n) g_dinv[i] = 1.0f;  // self-loop
}

__global__ void deg_count_kernel(const int* __restrict__ dst, int E) {
    for (int e = blockIdx.x * blockDim.x + threadIdx.x; e < E;
         e += gridDim.x * blockDim.x)
        atomicAdd(g_dinv + dst[e], 1.0f);
}

__global__ void deg_rsqrt_kernel(int n) {
    int i = blockIdx.x * blockDim.x + threadIdx.x;
    if (i < n) g_dinv[i] = rsqrtf(g_dinv[i]);
}

// ---------------------------------------------------------------------------
// Self-loop init: out[i,:] = bias + g_xw[i,:] * dinv[i]^2
// ---------------------------------------------------------------------------
template <int F>
__global__ void init_self_kernel(const float* __restrict__ bias,
                                 float* outp, int out_id, int n) {
    float* __restrict__ out = resolve(outp, out_id);
    const int F4 = F / 4;
    long long total = (long long)n * F4;
    for (long long i = blockIdx.x * (long long)blockDim.x + threadIdx.x; i < total;
         i += (long long)gridDim.x * blockDim.x) {
        int node = (int)(i / F4);
        int f = (int)(i % F4) * 4;
        float di = g_dinv[node];
        float s = di * di;
        float4 v = *(const float4*)(g_xw + (size_t)node * F + f);
        float4 b = *(const float4*)(bias + f);
        float4 o;
        o.x = fmaf(v.x, s, b.x);
        o.y = fmaf(v.y, s, b.y);
        o.z = fmaf(v.z, s, b.z);
        o.w = fmaf(v.w, s, b.w);
        *(float4*)(out + (size_t)node * F + f) = o;
    }
}

// ---------------------------------------------------------------------------
// Edge scatter: out[dst,:] += g_xw[src,:] * dinv[src]*dinv[dst]  (warp/edge)
// ---------------------------------------------------------------------------
template <int F>
__global__ void scatter_edges_kernel(const int* __restrict__ src,
                                     const int* __restrict__ dst,
                                     float* outp, int out_id, int E) {
    float* __restrict__ out = resolve(outp, out_id);
    int gwarp = (blockIdx.x * blockDim.x + threadIdx.x) >> 5;
    int lane = threadIdx.x & 31;
    int nwarps = (gridDim.x * blockDim.x) >> 5;
    for (int e = gwarp; e < E; e += nwarps) {
        int s = src[e];
        int d = dst[e];
        float c = g_dinv[s] * g_dinv[d];
        const float* xp = g_xw + (size_t)s * F;
        float* op = out + (size_t)d * F;
#pragma unroll
        for (int f = lane * 4; f < F; f += 128) {
            float4 v = *(const float4*)(xp + f);
            atomicAdd(op + f + 0, v.x * c);
            atomicAdd(op + f + 1, v.y * c);
            atomicAdd(op + f + 2, v.z * c);
            atomicAdd(op + f + 3, v.w * c);
        }
    }
}

// ---------------------------------------------------------------------------
// Segmented GEMM: C[M,Nout] = [A0|A1|A2] @ W (+bias) (+relu)
// A segments row-major with their own widths; W is [(K0+K1+K2) x Nout]
// row-major. Tile 64x64, BK=32, 256 threads, 4x4 per thread.
// ---------------------------------------------------------------------------
__device__ __forceinline__ float4 fetch_a4(const float* A0, int K0,
                                           const float* A1, int K1,
                                           const float* A2, int K2,
                                           int row, int k) {
    if (k < K0) return *(const float4*)(A0 + (size_t)row * K0 + k);
    k -= K0;
    if (k < K1) return *(const float4*)(A1 + (size_t)row * K1 + k);
    k -= K1;
    return *(const float4*)(A2 + (size_t)row * K2 + k);
}

template <bool RELU>
__global__ __launch_bounds__(256) void gemm_seg_kernel(
    const float* A0p, int id0, int K0,
    const float* A1p, int id1, int K1,
    const float* A2p, int id2, int K2,
    const float* __restrict__ W,
    const float* __restrict__ bias,  // may be null
    float* Cp, int idC, int M, int Nout) {
    const float* __restrict__ A0 = resolve_c(A0p, id0);
    const float* __restrict__ A1 = resolve_c(A1p, id1);
    const float* __restrict__ A2 = resolve_c(A2p, id2);
    float* __restrict__ C = resolve(Cp, idC);

    __shared__ __align__(16) float As[32][68];  // [k][row] transposed, padded
    __shared__ __align__(16) float Bs[32][64];  // [k][col]

    const int Ktot = K0 + K1 + K2;
    const int tid = threadIdx.x;
    const int bm = blockIdx.x * 64;
    const int bn = blockIdx.y * 64;
    const int tx = tid & 15;   // output cols tx*4..tx*4+3
    const int ty = tid >> 4;   // output rows ty*4..ty*4+3

    const int a_row = tid >> 3;          // 0..31
    const int a_col4 = (tid & 7) * 4;    // 0,4,..,28
    const int b_row = tid >> 4;          // 0..15
    const int b_col4 = (tid & 15) * 4;   // 0..60

    float acc[4][4] = {};

    for (int k0 = 0; k0 < Ktot; k0 += 32) {
#pragma unroll
        for (int rr = 0; rr < 2; rr++) {
            int row = bm + a_row + rr * 32;
            float4 v = make_float4(0.f, 0.f, 0.f, 0.f);
            if (row < M) v = fetch_a4(A0, K0, A1, K1, A2, K2, row, k0 + a_col4);
            As[a_col4 + 0][a_row + rr * 32] = v.x;
            As[a_col4 + 1][a_row + rr * 32] = v.y;
            As[a_col4 + 2][a_row + rr * 32] = v.z;
            As[a_col4 + 3][a_row + rr * 32] = v.w;
        }
#pragma unroll
        for (int rr = 0; rr < 2; rr++) {
            int k = k0 + b_row + rr * 16;
            float4 v = *(const float4*)(W + (size_t)k * Nout + bn + b_col4);
            *(float4*)&Bs[b_row + rr * 16][b_col4] = v;
        }
        __syncthreads();
#pragma unroll
        for (int kk = 0; kk < 32; kk++) {
            float4 a = *(float4*)&As[kk][ty * 4];
            float4 b = *(float4*)&Bs[kk][tx * 4];
            acc[0][0] = fmaf(a.x, b.x, acc[0][0]);
            acc[0][1] = fmaf(a.x, b.y, acc[0][1]);
            acc[0][2] = fmaf(a.x, b.z, acc[0][2]);
            acc[0][3] = fmaf(a.x, b.w, acc[0][3]);
            acc[1][0] = fmaf(a.y, b.x, acc[1][0]);
            acc[1][1] = fmaf(a.y, b.y, acc[1][1]);
            acc[1][2] = fmaf(a.y, b.z, acc[1][2]);
            acc[1][3] = fmaf(a.y, b.w, acc[1][3]);
            acc[2][0] = fmaf(a.z, b.x, acc[2][0]);
            acc[2][1] = fmaf(a.z, b.y, acc[2][1]);
            acc[2][2] = fmaf(a.z, b.z, acc[2][2]);
            acc[2][3] = fmaf(a.z, b.w, acc[2][3]);
            acc[3][0] = fmaf(a.w, b.x, acc[3][0]);
            acc[3][1] = fmaf(a.w, b.y, acc[3][1]);
            acc[3][2] = fmaf(a.w, b.z, acc[3][2]);
            acc[3][3] = fmaf(a.w, b.w, acc[3][3]);
        }
        __syncthreads();
    }

    float4 bv = make_float4(0.f, 0.f, 0.f, 0.f);
    if (bias) bv = *(const float4*)(bias + bn + tx * 4);
#pragma unroll
    for (int i = 0; i < 4; i++) {
        int row = bm + ty * 4 + i;
        if (row >= M) continue;
        float4 o;
        o.x = acc[i][0] + bv.x;
        o.y = acc[i][1] + bv.y;
        o.z = acc[i][2] + bv.z;
        o.w = acc[i][3] + bv.w;
        if (RELU) {
            o.x = fmaxf(o.x, 0.f);
            o.y = fmaxf(o.y, 0.f);
            o.z = fmaxf(o.z, 0.f);
            o.w = fmaxf(o.w, 0.f);
        }
        *(float4*)(C + (size_t)row * Nout + bn + tx * 4) = o;
    }
}

// ---------------------------------------------------------------------------
// Launch
// ---------------------------------------------------------------------------
extern "C" void kernel_launch(void* const* d_in, const int* in_sizes, int n_in,
                              void* d_out, int out_size) {
    const float* x_self = (const float*)d_in[0];
    const float* x_nb   = (const float*)d_in[1];
    // edge_index: JAX emits int32 here (x64 disabled -> randint int64 request
    // silently downcasts to int32).
    const int* ei = (const int*)d_in[2];
    const float* W_in_self  = (const float*)d_in[3];
    const float* b_in_self  = (const float*)d_in[4];
    const float* W_out_self = (const float*)d_in[5];
    const float* b_out_self = (const float*)d_in[6];
    const float* Wg1 = (const float*)d_in[7];
    const float* bg1 = (const float*)d_in[8];
    const float* Wg2 = (const float*)d_in[9];
    const float* bg2 = (const float*)d_in[10];
    const float* W_out = (const float*)d_in[11];
    const float* b_out = (const float*)d_in[12];

    const int N = in_sizes[0] / 128;
    const int E = in_sizes[2] / 2;
    const int* src = ei;
    const int* dst = ei + E;

    float* out_l1 = (float*)d_out;
    float* out_x2 = (float*)d_out + (size_t)N * 128;

    const int T = 256;
    const int gN = (N + T - 1) / T;
    const dim3 gemmBlk(256);
    const int gemmMx = (N + 63) / 64;

    // 1. degree normalization (shared by both GCN layers)
    deg_init_kernel<<<gN, T>>>(N);
    deg_count_kernel<<<1024, T>>>(dst, E);
    deg_rsqrt_kernel<<<gN, T>>>(N);

    // 2. dense self branch: l1a = relu(x_self@W_in_self + b) -> g_xw
    gemm_seg_kernel<true><<<dim3(gemmMx, 4), gemmBlk>>>(
        x_self, BUF_NONE, 128, nullptr, BUF_NONE, 0, nullptr, BUF_NONE, 0,
        W_in_self, b_in_self, nullptr, BUF_XW, N, 256);
    //    l1 = [x_self | l1a] @ W_out_self + b -> out_l1
    gemm_seg_kernel<false><<<dim3(gemmMx, 2), gemmBlk>>>(
        x_self, BUF_NONE, 128, nullptr, BUF_XW, 256, nullptr, BUF_NONE, 0,
        W_out_self, b_out_self, out_l1, BUF_NONE, N, 128);

    // 3. gcn1: xw1 = x_nb @ Wg1 (bias folded into init_self)
    gemm_seg_kernel<false><<<dim3(gemmMx, 4), gemmBlk>>>(
        x_nb, BUF_NONE, 128, nullptr, BUF_NONE, 0, nullptr, BUF_NONE, 0,
        Wg1, nullptr, nullptr, BUF_XW, N, 256);
    init_self_kernel<256><<<2048, T>>>(bg1, nullptr, BUF_G1, N);
    scatter_edges_kernel<256><<<2048, T>>>(src, dst, nullptr, BUF_G1, E);

    // 4. gcn2: xw2 = g1 @ Wg2 (reuse g_xw, only N*128 used)
    gemm_seg_kernel<false><<<dim3(gemmMx, 2), gemmBlk>>>(
        nullptr, BUF_G1, 256, nullptr, BUF_NONE, 0, nullptr, BUF_NONE, 0,
        Wg2, nullptr, nullptr, BUF_XW, N, 128);
    init_self_kernel<128><<<2048, T>>>(bg2, nullptr, BUF_G2, N);
    scatter_edges_kernel<128><<<2048, T>>>(src, dst, nullptr, BUF_G2, E);

    // 5. x2 = [x_nb | g1 | g2] @ W_out + b -> out_x2
    gemm_seg_kernel<false><<<dim3(gemmMx, 2), gemmBlk>>>(
        x_nb, BUF_NONE, 128, nullptr, BUF_G1, 256, nullptr, BUF_G2, 128,
        W_out, b_out, out_x2, BUF_NONE, N, 128);
}

// round 8
// speedup vs baseline: 2.0079x; 2.0079x over previous
#include <cuda_runtime.h>
#include <cstdint>

// Problem constants (fixed by the dataset): N=100000 nodes, E=1600000, D=C=128.
#define NN 100000
#define EE 1600000

// Scratch (device globals — no allocations allowed anywhere).
__device__ __align__(16) float g_dinv[NN];              // rsqrt(degree)
__device__ __align__(16) float g_xw[(size_t)NN * 256];  // reused: l1a, xw1, xw2
__device__ __align__(16) float g_g1[(size_t)NN * 256];  // gcn1 output
__device__ __align__(16) float g_g2[(size_t)NN * 128];  // gcn2 output
__device__ int g_rowcnt[NN];        // in-degree histogram
__device__ int g_rowstart[NN + 1];  // CSR row offsets
__device__ int g_rowfill[NN];       // fill cursors
__device__ int g_csr_src[EE];       // CSR column (source node) indices

#define BUF_NONE 0
#define BUF_XW   1
#define BUF_G1   2
#define BUF_G2   3

__device__ __forceinline__ float* resolve(float* p, int id) {
    switch (id) {
        case BUF_XW: return g_xw;
        case BUF_G1: return g_g1;
        case BUF_G2: return g_g2;
        default: return p;
    }
}
__device__ __forceinline__ const float* resolve_c(const float* p, int id) {
    switch (id) {
        case BUF_XW: return g_xw;
        case BUF_G1: return g_g1;
        case BUF_G2: return g_g2;
        default: return p;
    }
}

// ---------------------------------------------------------------------------
// CSR construction
// ---------------------------------------------------------------------------
__global__ void zero_cnt_kernel(int n) {
    int i = blockIdx.x * blockDim.x + threadIdx.x;
    if (i < n) g_rowcnt[i] = 0;
}

__global__ void count_dst_kernel(const int* __restrict__ dst, int E) {
    for (int e = blockIdx.x * blockDim.x + threadIdx.x; e < E;
         e += gridDim.x * blockDim.x)
        atomicAdd(g_rowcnt + dst[e], 1);
}

// Single-block exclusive scan over g_rowcnt; also derives dinv and fill ptrs.
__global__ __launch_bounds__(1024) void scan_kernel(int n) {
    __shared__ int sums[1024];
    const int tid = threadIdx.x;
    const int chunk = (n + 1023) >> 10;
    const int begin = tid * chunk;
    const int end = min(begin + chunk, n);

    int s = 0;
    for (int i = begin; i < end; i++) s += g_rowcnt[i];
    sums[tid] = s;
    __syncthreads();
#pragma unroll
    for (int off = 1; off < 1024; off <<= 1) {
        int add = (tid >= off) ? sums[tid - off] : 0;
        __syncthreads();
        sums[tid] += add;
        __syncthreads();
    }
    if (tid == 0) g_rowstart[n] = sums[1023];
    int prefix = (tid > 0) ? sums[tid - 1] : 0;
    for (int i = begin; i < end; i++) {
        int c = g_rowcnt[i];
        g_rowstart[i] = prefix;
        g_rowfill[i] = prefix;
        g_dinv[i] = rsqrtf((float)(c + 1));  // +1 self loop
        prefix += c;
    }
}

__global__ void csr_fill_kernel(const int* __restrict__ src,
                                const int* __restrict__ dst, int E) {
    for (int e = blockIdx.x * blockDim.x + threadIdx.x; e < E;
         e += gridDim.x * blockDim.x) {
        int d = dst[e];
        int pos = atomicAdd(g_rowfill + d, 1);
        g_csr_src[pos] = src[e];
    }
}

// ---------------------------------------------------------------------------
// Gather aggregation (one warp per destination node), self-loop+bias fused:
//   out[d,:] = bias + g_xw[d,:]*dinv[d]^2 + sum_e g_xw[src,:]*dinv[src]*dinv[d]
// ---------------------------------------------------------------------------
template <int F>
__global__ void gather_agg_kernel(const float* __restrict__ bias,
                                  float* outp, int out_id, int n) {
    float* __restrict__ out = resolve(outp, out_id);
    const int warp = (blockIdx.x * blockDim.x + threadIdx.x) >> 5;
    const int lane = threadIdx.x & 31;
    if (warp >= n) return;
    const int node = warp;
    const int f0 = lane * 4;
    constexpr int NH = F / 128;

    const float din = g_dinv[node];
    const float s2 = din * din;
    const float* xn = g_xw + (size_t)node * F;

    float4 acc[NH];
#pragma unroll
    for (int h = 0; h < NH; h++) {
        float4 v = *(const float4*)(xn + f0 + h * 128);
        float4 b = *(const float4*)(bias + f0 + h * 128);
        acc[h].x = fmaf(v.x, s2, b.x);
        acc[h].y = fmaf(v.y, s2, b.y);
        acc[h].z = fmaf(v.z, s2, b.z);
        acc[h].w = fmaf(v.w, s2, b.w);
    }

    const int rs = g_rowstart[node];
    const int re = g_rowstart[node + 1];
    for (int e = rs; e < re; e++) {
        int s = g_csr_src[e];
        float c = g_dinv[s] * din;
        const float* xp = g_xw + (size_t)s * F;
#pragma unroll
        for (int h = 0; h < NH; h++) {
            float4 v = *(const float4*)(xp + f0 + h * 128);
            acc[h].x = fmaf(v.x, c, acc[h].x);
            acc[h].y = fmaf(v.y, c, acc[h].y);
            acc[h].z = fmaf(v.z, c, acc[h].z);
            acc[h].w = fmaf(v.w, c, acc[h].w);
        }
    }

    float* op = out + (size_t)node * F;
#pragma unroll
    for (int h = 0; h < NH; h++) *(float4*)(op + f0 + h * 128) = acc[h];
}

// ---------------------------------------------------------------------------
// Segmented GEMM: C[M,Nout] = [A0|A1|A2] @ W (+bias) (+relu)
// 128x128 tile, BK=8, 256 threads, 8x8 per thread (4+64 split fragments).
// ---------------------------------------------------------------------------
__device__ __forceinline__ float4 fetch_a4(const float* A0, int K0,
                                           const float* A1, int K1,
                                           const float* A2, int K2,
                                           int row, int k) {
    if (k < K0) return *(const float4*)(A0 + (size_t)row * K0 + k);
    k -= K0;
    if (k < K1) return *(const float4*)(A1 + (size_t)row * K1 + k);
    k -= K1;
    return *(const float4*)(A2 + (size_t)row * K2 + k);
}

template <bool RELU>
__global__ __launch_bounds__(256, 2) void gemm_seg_kernel(
    const float* A0p, int id0, int K0,
    const float* A1p, int id1, int K1,
    const float* A2p, int id2, int K2,
    const float* __restrict__ W,
    const float* __restrict__ bias,  // may be null
    float* Cp, int idC, int M, int Nout) {
    const float* __restrict__ A0 = resolve_c(A0p, id0);
    const float* __restrict__ A1 = resolve_c(A1p, id1);
    const float* __restrict__ A2 = resolve_c(A2p, id2);
    float* __restrict__ C = resolve(Cp, idC);

    __shared__ __align__(16) float As[8][132];  // [k][m] transposed, padded
    __shared__ __align__(16) float Bs[8][128];  // [k][n]

    const int Ktot = K0 + K1 + K2;
    const int tid = threadIdx.x;
    const int bm = blockIdx.x * 128;
    const int bn = blockIdx.y * 128;

    const int am = tid >> 1;          // 0..127
    const int ak = (tid & 1) * 4;     // 0 or 4
    const int bk = tid >> 5;          // 0..7
    const int bn4 = (tid & 31) * 4;   // 0..124

    const int tx4 = (tid & 15) * 4;   // col frag base (and +64)
    const int ty4 = (tid >> 4) * 4;   // row frag base (and +64)

    const int arow = bm + am;
    const bool aok = arow < M;

    float acc[2][2][4][4] = {};

    for (int k0 = 0; k0 < Ktot; k0 += 8) {
        float4 av = aok ? fetch_a4(A0, K0, A1, K1, A2, K2, arow, k0 + ak)
                        : make_float4(0.f, 0.f, 0.f, 0.f);
        float4 wv = *(const float4*)(W + (size_t)(k0 + bk) * Nout + bn + bn4);
        __syncthreads();
        As[ak + 0][am] = av.x;
        As[ak + 1][am] = av.y;
        As[ak + 2][am] = av.z;
        As[ak + 3][am] = av.w;
        *(float4*)&Bs[bk][bn4] = wv;
        __syncthreads();
#pragma unroll
        for (int kk = 0; kk < 8; kk++) {
            float4 a0 = *(float4*)&As[kk][ty4];
            float4 a1 = *(float4*)&As[kk][ty4 + 64];
            float4 b0 = *(float4*)&Bs[kk][tx4];
            float4 b1 = *(float4*)&Bs[kk][tx4 + 64];
            float ar[2][4] = {{a0.x, a0.y, a0.z, a0.w}, {a1.x, a1.y, a1.z, a1.w}};
            float br[2][4] = {{b0.x, b0.y, b0.z, b0.w}, {b1.x, b1.y, b1.z, b1.w}};
#pragma unroll
            for (int rg = 0; rg < 2; rg++)
#pragma unroll
                for (int cg = 0; cg < 2; cg++)
#pragma unroll
                    for (int i = 0; i < 4; i++)
#pragma unroll
                        for (int j = 0; j < 4; j++)
                            acc[rg][cg][i][j] =
                                fmaf(ar[rg][i], br[cg][j], acc[rg][cg][i][j]);
        }
    }

    float4 bv[2] = {make_float4(0.f, 0.f, 0.f, 0.f),
                    make_float4(0.f, 0.f, 0.f, 0.f)};
    if (bias) {
        bv[0] = *(const float4*)(bias + bn + tx4);
        bv[1] = *(const float4*)(bias + bn + tx4 + 64);
    }
#pragma unroll
    for (int rg = 0; rg < 2; rg++) {
#pragma unroll
        for (int i = 0; i < 4; i++) {
            int row = bm + ty4 + rg * 64 + i;
            if (row >= M) continue;
#pragma unroll
            for (int cg = 0; cg < 2; cg++) {
                float4 o;
                o.x = acc[rg][cg][i][0] + bv[cg].x;
                o.y = acc[rg][cg][i][1] + bv[cg].y;
                o.z = acc[rg][cg][i][2] + bv[cg].z;
                o.w = acc[rg][cg][i][3] + bv[cg].w;
                if (RELU) {
                    o.x = fmaxf(o.x, 0.f);
                    o.y = fmaxf(o.y, 0.f);
                    o.z = fmaxf(o.z, 0.f);
                    o.w = fmaxf(o.w, 0.f);
                }
                *(float4*)(C + (size_t)row * Nout + bn + tx4 + cg * 64) = o;
            }
        }
    }
}

// ---------------------------------------------------------------------------
// Launch
// ---------------------------------------------------------------------------
extern "C" void kernel_launch(void* const* d_in, const int* in_sizes, int n_in,
                              void* d_out, int out_size) {
    const float* x_self = (const float*)d_in[0];
    const float* x_nb   = (const float*)d_in[1];
    const int* ei = (const int*)d_in[2];  // int32 (JAX x64 disabled)
    const float* W_in_self  = (const float*)d_in[3];
    const float* b_in_self  = (const float*)d_in[4];
    const float* W_out_self = (const float*)d_in[5];
    const float* b_out_self = (const float*)d_in[6];
    const float* Wg1 = (const float*)d_in[7];
    const float* bg1 = (const float*)d_in[8];
    const float* Wg2 = (const float*)d_in[9];
    const float* bg2 = (const float*)d_in[10];
    const float* W_out = (const float*)d_in[11];
    const float* b_out = (const float*)d_in[12];

    const int N = in_sizes[0] / 128;
    const int E = in_sizes[2] / 2;
    const int* src = ei;
    const int* dst = ei + E;

    float* out_l1 = (float*)d_out;
    float* out_x2 = (float*)d_out + (size_t)N * 128;

    const int T = 256;
    const int gN = (N + T - 1) / T;
    const int gemmMx = (N + 127) / 128;
    const int gatherBlocks = (N + 7) / 8;  // 8 warps/block, warp per node

    // 1. CSR build + degree normalization
    zero_cnt_kernel<<<gN, T>>>(N);
    count_dst_kernel<<<1024, T>>>(dst, E);
    scan_kernel<<<1, 1024>>>(N);
    csr_fill_kernel<<<1024, T>>>(src, dst, E);

    // 2. dense self branch: l1a = relu(x_self@W_in_self + b) -> g_xw
    gemm_seg_kernel<true><<<dim3(gemmMx, 2), T>>>(
        x_self, BUF_NONE, 128, nullptr, BUF_NONE, 0, nullptr, BUF_NONE, 0,
        W_in_self, b_in_self, nullptr, BUF_XW, N, 256);
    //    l1 = [x_self | l1a] @ W_out_self + b -> out_l1
    gemm_seg_kernel<false><<<dim3(gemmMx, 1), T>>>(
        x_self, BUF_NONE, 128, nullptr, BUF_XW, 256, nullptr, BUF_NONE, 0,
        W_out_self, b_out_self, out_l1, BUF_NONE, N, 128);

    // 3. gcn1: xw1 = x_nb @ Wg1 -> g_xw ; g1 = bias + selfloop + gather
    gemm_seg_kernel<false><<<dim3(gemmMx, 2), T>>>(
        x_nb, BUF_NONE, 128, nullptr, BUF_NONE, 0, nullptr, BUF_NONE, 0,
        Wg1, nullptr, nullptr, BUF_XW, N, 256);
    gather_agg_kernel<256><<<gatherBlocks, T>>>(bg1, nullptr, BUF_G1, N);

    // 4. gcn2: xw2 = g1 @ Wg2 -> g_xw ; g2 = bias + selfloop + gather
    gemm_seg_kernel<false><<<dim3(gemmMx, 1), T>>>(
        nullptr, BUF_G1, 256, nullptr, BUF_NONE, 0, nullptr, BUF_NONE, 0,
        Wg2, nullptr, nullptr, BUF_XW, N, 128);
    gather_agg_kernel<128><<<gatherBlocks, T>>>(bg2, nullptr, BUF_G2, N);

    // 5. x2 = [x_nb | g1 | g2] @ W_out + b -> out_x2
    gemm_seg_kernel<false><<<dim3(gemmMx, 1), T>>>(
        x_nb, BUF_NONE, 128, nullptr, BUF_G1, 256, nullptr, BUF_G2, 128,
        W_out, b_out, out_x2, BUF_NONE, N, 128);
}